// round 1
// baseline (speedup 1.0000x reference)
#include <cuda_runtime.h>

#define N_NODES 100000
#define D 128
#define MT 128            // nodes per GEMM block
#define WS_STRIDE 132     // padded W row stride in shared (floats)
#define GEMM_SMEM_BYTES ((MT * D + D * WS_STRIDE) * 4)

// Scratch (allocation-free rule: __device__ globals)
__device__ int   g_row_ptr[N_NODES + 1];
__device__ float g_agg[(size_t)N_NODES * D];

// ---------------------------------------------------------------------------
// Kernel 1: build CSR row pointers from sorted edge_rows
// ---------------------------------------------------------------------------
__global__ void build_row_ptr_kernel(const int* __restrict__ rows, int E) {
    int e = blockIdx.x * blockDim.x + threadIdx.x;
    if (e >= E) return;
    int r  = rows[e];
    int rp = (e == 0) ? -1 : rows[e - 1];
    for (int j = rp + 1; j <= r; j++) g_row_ptr[j] = e;
    if (e == E - 1) {
        for (int j = r + 1; j <= N_NODES; j++) g_row_ptr[j] = E;
    }
}

// ---------------------------------------------------------------------------
// Kernel 2: SpMM — one warp per node, lane owns 4 columns (float4)
// ---------------------------------------------------------------------------
__global__ void __launch_bounds__(256) spmm_kernel(const int*   __restrict__ cols,
                                                   const float* __restrict__ vals,
                                                   const float* __restrict__ h) {
    int gwarp = (blockIdx.x * blockDim.x + threadIdx.x) >> 5;
    int lane  = threadIdx.x & 31;
    if (gwarp >= N_NODES) return;

    int s = g_row_ptr[gwarp];
    int e = g_row_ptr[gwarp + 1];

    float4 acc = make_float4(0.f, 0.f, 0.f, 0.f);
    #pragma unroll 4
    for (int i = s; i < e; i++) {
        int   c = __ldg(&cols[i]);          // warp-uniform broadcast
        float v = __ldg(&vals[i]);          // warp-uniform broadcast
        float4 hv = __ldg((const float4*)(h + (size_t)c * D) + lane); // coalesced 512B
        acc.x += v * hv.x;
        acc.y += v * hv.y;
        acc.z += v * hv.z;
        acc.w += v * hv.w;
    }
    ((float4*)(g_agg + (size_t)gwarp * D))[lane] = acc;
}

// ---------------------------------------------------------------------------
// Kernel 3: out = relu(agg @ W^T + b)
// 256 threads / block, block computes 128 nodes x 128 cols,
// thread computes 8 nodes x 8 cols (register tile), K chunked by 4.
// ---------------------------------------------------------------------------
__global__ void __launch_bounds__(256) gemm_bias_relu_kernel(const float* __restrict__ W,
                                                             const float* __restrict__ b,
                                                             float* __restrict__ out) {
    extern __shared__ float sm[];
    float* As = sm;                // [MT][D]        (stride D; reads are warp-broadcast)
    float* Ws = sm + MT * D;       // [D][WS_STRIDE] (padded to avoid bank conflicts)

    const int tid   = threadIdx.x;          // 0..255
    const int node0 = blockIdx.x * MT;

    // Load W (row-major [j][k]) into padded shared, coalesced float4 reads.
    for (int i = tid; i < (D * D) / 4; i += 256) {
        float4 w4 = ((const float4*)W)[i];
        int j = (i * 4) / D;
        int k = (i * 4) % D;
        *(float4*)(Ws + j * WS_STRIDE + k) = w4;   // j*132+k: 16B-aligned, conflict-free stores
    }
    // Load agg tile [MT][D], zero-pad out-of-range nodes.
    for (int i = tid; i < (MT * D) / 4; i += 256) {
        int n = (i * 4) / D;
        int k = (i * 4) % D;
        int gn = node0 + n;
        float4 a4 = (gn < N_NODES)
                  ? ((const float4*)(g_agg + (size_t)gn * D))[k >> 2]
                  : make_float4(0.f, 0.f, 0.f, 0.f);
        *(float4*)(As + n * D + k) = a4;
    }
    __syncthreads();

    const int tx = tid & 15;       // column group: cols j = tx*8 + jj
    const int ty = tid >> 4;       // node   group: nodes n = ty*8 + nn

    float acc[8][8];
    #pragma unroll
    for (int nn = 0; nn < 8; nn++)
        #pragma unroll
        for (int jj = 0; jj < 8; jj++)
            acc[nn][jj] = 0.f;

    #pragma unroll 8
    for (int k = 0; k < D; k += 4) {
        float4 a4[8];
        float4 w4[8];
        #pragma unroll
        for (int nn = 0; nn < 8; nn++)
            a4[nn] = *(const float4*)(As + (ty * 8 + nn) * D + k);       // warp-broadcast
        #pragma unroll
        for (int jj = 0; jj < 8; jj++)
            w4[jj] = *(const float4*)(Ws + (tx * 8 + jj) * WS_STRIDE + k); // padded, ~conflict-free
        #pragma unroll
        for (int nn = 0; nn < 8; nn++)
            #pragma unroll
            for (int jj = 0; jj < 8; jj++)
                acc[nn][jj] += a4[nn].x * w4[jj].x + a4[nn].y * w4[jj].y
                             + a4[nn].z * w4[jj].z + a4[nn].w * w4[jj].w;
    }

    // Epilogue: + b, relu, float4 stores.
    float bb[8];
    #pragma unroll
    for (int jj = 0; jj < 8; jj++)
        bb[jj] = __ldg(&b[tx * 8 + jj]);

    #pragma unroll
    for (int nn = 0; nn < 8; nn++) {
        int gn = node0 + ty * 8 + nn;
        if (gn < N_NODES) {
            #pragma unroll
            for (int jj4 = 0; jj4 < 8; jj4 += 4) {
                float4 o;
                o.x = fmaxf(acc[nn][jj4 + 0] + bb[jj4 + 0], 0.f);
                o.y = fmaxf(acc[nn][jj4 + 1] + bb[jj4 + 1], 0.f);
                o.z = fmaxf(acc[nn][jj4 + 2] + bb[jj4 + 2], 0.f);
                o.w = fmaxf(acc[nn][jj4 + 3] + bb[jj4 + 3], 0.f);
                *(float4*)(out + (size_t)gn * D + tx * 8 + jj4) = o;
            }
        }
    }
}

// ---------------------------------------------------------------------------
// Launch
// ---------------------------------------------------------------------------
extern "C" void kernel_launch(void* const* d_in, const int* in_sizes, int n_in,
                              void* d_out, int out_size) {
    const int*   edge_rows = (const int*)  d_in[0];
    const int*   edge_cols = (const int*)  d_in[1];
    const float* edge_vals = (const float*)d_in[2];
    const float* h         = (const float*)d_in[3];
    const float* W         = (const float*)d_in[4];
    const float* b         = (const float*)d_in[5];
    float*       out       = (float*)d_out;
    const int E = in_sizes[0];

    // 1) CSR row pointers
    build_row_ptr_kernel<<<(E + 255) / 256, 256>>>(edge_rows, E);

    // 2) SpMM: one warp per node -> 100000 warps
    {
        long long total_threads = (long long)N_NODES * 32;
        int blocks = (int)((total_threads + 255) / 256);
        spmm_kernel<<<blocks, 256>>>(edge_cols, edge_vals, h);
    }

    // 3) GEMM + bias + relu
    cudaFuncSetAttribute(gemm_bias_relu_kernel,
                         cudaFuncAttributeMaxDynamicSharedMemorySize,
                         GEMM_SMEM_BYTES);
    gemm_bias_relu_kernel<<<(N_NODES + MT - 1) / MT, 256, GEMM_SMEM_BYTES>>>(W, b, out);
}

// round 2
// speedup vs baseline: 1.5400x; 1.5400x over previous
#include <cuda_runtime.h>

#define N_NODES 100000
#define D 128
#define MT 128                                   // nodes per GEMM block
#define GEMM_SMEM_BYTES ((MT * D + D * D) * 4)   // As + Ws = 128KB

// Scratch (allocation-free rule: __device__ globals)
__device__ int   g_row_ptr[N_NODES + 1];
__device__ float g_agg[(size_t)N_NODES * D];
__device__ float g_Wt[D * D];                    // W transposed: [k][j]

// ---------------------------------------------------------------------------
// Kernel 1: build CSR row pointers from sorted edge_rows (shfl for neighbor)
// ---------------------------------------------------------------------------
__global__ void build_row_ptr_kernel(const int* __restrict__ rows, int E) {
    int e    = blockIdx.x * blockDim.x + threadIdx.x;
    int lane = threadIdx.x & 31;
    int ee   = min(e, E - 1);
    int r    = rows[ee];
    int rp   = 0;
    if (lane == 0 && ee > 0) rp = rows[ee - 1];
    int rs = __shfl_up_sync(0xffffffff, r, 1);
    if (lane > 0) rp = rs;
    if (e >= E) return;
    if (e == 0) rp = -1;
    for (int j = rp + 1; j <= r; j++) g_row_ptr[j] = e;
    if (e == E - 1) {
        for (int j = r + 1; j <= N_NODES; j++) g_row_ptr[j] = E;
    }
}

// ---------------------------------------------------------------------------
// Kernel 2: transpose W ([j][k] row-major) -> g_Wt ([k][j])
// ---------------------------------------------------------------------------
__global__ void transpose_w_kernel(const float* __restrict__ W) {
    int j = blockIdx.x;          // 128 blocks
    int k = threadIdx.x;         // 128 threads
    g_Wt[k * D + j] = W[j * D + k];
}

// ---------------------------------------------------------------------------
// Kernel 3: SpMM — one warp per node; metadata fetched cooperatively
// (1 coalesced load per 32 edges) and distributed via shuffle.
// ---------------------------------------------------------------------------
__global__ void __launch_bounds__(256) spmm_kernel(const int*   __restrict__ cols,
                                                   const float* __restrict__ vals,
                                                   const float* __restrict__ h) {
    int gwarp = (blockIdx.x * blockDim.x + threadIdx.x) >> 5;
    int lane  = threadIdx.x & 31;
    if (gwarp >= N_NODES) return;

    int s = g_row_ptr[gwarp];
    int e = g_row_ptr[gwarp + 1];

    float4 acc = make_float4(0.f, 0.f, 0.f, 0.f);

    for (int base = s; base < e; base += 32) {
        int   idx = base + lane;
        int   c   = 0;
        float v   = 0.f;
        if (idx < e) {
            c = __ldg(&cols[idx]);     // coalesced
            v = __ldg(&vals[idx]);     // coalesced
        }
        int cnt = min(32, e - base);
        #pragma unroll 4
        for (int j = 0; j < cnt; j++) {
            int   cc = __shfl_sync(0xffffffff, c, j);
            float vv = __shfl_sync(0xffffffff, v, j);
            float4 hv = __ldg((const float4*)(h + (size_t)cc * D) + lane); // 512B coalesced
            acc.x += vv * hv.x;
            acc.y += vv * hv.y;
            acc.z += vv * hv.z;
            acc.w += vv * hv.w;
        }
    }
    ((float4*)(g_agg + (size_t)gwarp * D))[lane] = acc;
}

// ---------------------------------------------------------------------------
// Kernel 4: out = relu(agg @ W^T + b), outer-product style.
// 256 threads; block tile 128 nodes x 128 cols; thread tile 8 nodes x 8 cols
// (cols split as {4tx..4tx+3} and {64+4tx..64+4tx+3} -> 2-way LDS max).
// ---------------------------------------------------------------------------
__global__ void __launch_bounds__(256) gemm_bias_relu_kernel(const float* __restrict__ b,
                                                             float* __restrict__ out) {
    extern __shared__ float sm[];
    float* As = sm;             // [MT][D]  node-major (reads are ty-broadcast)
    float* Ws = sm + MT * D;    // [D][D]   k-major   (reads 2-way max)

    const int tid   = threadIdx.x;     // 0..255
    const int node0 = blockIdx.x * MT;
    const int tx    = tid & 15;        // 16 col groups
    const int ty    = tid >> 4;        // 16 node groups

    // Load Wt (k-major, contiguous) into shared — fully coalesced, conflict-free.
    for (int i = tid; i < (D * D) / 4; i += 256)
        ((float4*)Ws)[i] = ((const float4*)g_Wt)[i];

    // Load agg tile [MT][D], zero-pad out-of-range nodes.
    for (int i = tid; i < (MT * D) / 4; i += 256) {
        int n  = (i * 4) / D;
        int gn = node0 + n;
        float4 a4 = (gn < N_NODES)
                  ? ((const float4*)(g_agg + (size_t)gn * D))[(i * 4 % D) >> 2]
                  : make_float4(0.f, 0.f, 0.f, 0.f);
        ((float4*)As)[i] = a4;
    }
    __syncthreads();

    float acc[8][8];
    #pragma unroll
    for (int nn = 0; nn < 8; nn++)
        #pragma unroll
        for (int jj = 0; jj < 8; jj++)
            acc[nn][jj] = 0.f;

    for (int kk = 0; kk < D; kk += 4) {
        float4 a4[8];
        float4 wA[4], wB[4];
        #pragma unroll
        for (int nn = 0; nn < 8; nn++)
            a4[nn] = *(const float4*)(As + (ty * 8 + nn) * D + kk);      // broadcast
        #pragma unroll
        for (int t = 0; t < 4; t++) {
            wA[t] = *(const float4*)(Ws + (kk + t) * D + tx * 4);        // 2-way
            wB[t] = *(const float4*)(Ws + (kk + t) * D + 64 + tx * 4);   // 2-way
        }
        #pragma unroll
        for (int t = 0; t < 4; t++) {
            #pragma unroll
            for (int nn = 0; nn < 8; nn++) {
                float a = (t == 0) ? a4[nn].x : (t == 1) ? a4[nn].y
                        : (t == 2) ? a4[nn].z : a4[nn].w;
                acc[nn][0] += a * wA[t].x;
                acc[nn][1] += a * wA[t].y;
                acc[nn][2] += a * wA[t].z;
                acc[nn][3] += a * wA[t].w;
                acc[nn][4] += a * wB[t].x;
                acc[nn][5] += a * wB[t].y;
                acc[nn][6] += a * wB[t].z;
                acc[nn][7] += a * wB[t].w;
            }
        }
    }

    // Epilogue: + b, relu, two float4 stores per node.
    float4 bA = *(const float4*)(b + tx * 4);
    float4 bB = *(const float4*)(b + 64 + tx * 4);

    #pragma unroll
    for (int nn = 0; nn < 8; nn++) {
        int gn = node0 + ty * 8 + nn;
        if (gn < N_NODES) {
            float4 oA, oB;
            oA.x = fmaxf(acc[nn][0] + bA.x, 0.f);
            oA.y = fmaxf(acc[nn][1] + bA.y, 0.f);
            oA.z = fmaxf(acc[nn][2] + bA.z, 0.f);
            oA.w = fmaxf(acc[nn][3] + bA.w, 0.f);
            oB.x = fmaxf(acc[nn][4] + bB.x, 0.f);
            oB.y = fmaxf(acc[nn][5] + bB.y, 0.f);
            oB.z = fmaxf(acc[nn][6] + bB.z, 0.f);
            oB.w = fmaxf(acc[nn][7] + bB.w, 0.f);
            *(float4*)(out + (size_t)gn * D + tx * 4)      = oA;
            *(float4*)(out + (size_t)gn * D + 64 + tx * 4) = oB;
        }
    }
}

// ---------------------------------------------------------------------------
// Launch
// ---------------------------------------------------------------------------
extern "C" void kernel_launch(void* const* d_in, const int* in_sizes, int n_in,
                              void* d_out, int out_size) {
    const int*   edge_rows = (const int*)  d_in[0];
    const int*   edge_cols = (const int*)  d_in[1];
    const float* edge_vals = (const float*)d_in[2];
    const float* h         = (const float*)d_in[3];
    const float* W         = (const float*)d_in[4];
    const float* b         = (const float*)d_in[5];
    float*       out       = (float*)d_out;
    const int E = in_sizes[0];

    // 1) CSR row pointers
    build_row_ptr_kernel<<<(E + 255) / 256, 256>>>(edge_rows, E);

    // 2) W transpose (k-major) for conflict-free GEMM loads
    transpose_w_kernel<<<D, D>>>(W);

    // 3) SpMM: one warp per node
    {
        long long total_threads = (long long)N_NODES * 32;
        int blocks = (int)((total_threads + 255) / 256);
        spmm_kernel<<<blocks, 256>>>(edge_cols, edge_vals, h);
    }

    // 4) GEMM + bias + relu
    cudaFuncSetAttribute(gemm_bias_relu_kernel,
                         cudaFuncAttributeMaxDynamicSharedMemorySize,
                         GEMM_SMEM_BYTES);
    gemm_bias_relu_kernel<<<(N_NODES + MT - 1) / MT, 256, GEMM_SMEM_BYTES>>>(b, out);
}

// round 3
// speedup vs baseline: 1.7488x; 1.1356x over previous
#include <cuda_runtime.h>

#define N_NODES 100000
#define D 128
#define MT 128                                   // nodes per GEMM block
#define GEMM_SMEM_BYTES ((MT * D + D * D) * 4)   // As + Ws = 128KB

typedef unsigned long long u64;

// Scratch (allocation-free rule: __device__ globals)
__device__ int   g_row_ptr[N_NODES + 1];
__device__ float g_agg[(size_t)N_NODES * D];
__device__ float g_Wt[D * D];                    // W transposed: [k][j]

// ---- packed f32x2 helpers (sm_100+) ---------------------------------------
__device__ __forceinline__ u64 pack2(float x, float y) {
    u64 r; asm("mov.b64 %0, {%1, %2};" : "=l"(r) : "f"(x), "f"(y)); return r;
}
__device__ __forceinline__ u64 fma2(u64 a, u64 b, u64 c) {
    u64 d; asm("fma.rn.f32x2 %0, %1, %2, %3;" : "=l"(d) : "l"(a), "l"(b), "l"(c));
    return d;
}
__device__ __forceinline__ float2 unpack2(u64 v) {
    float2 f; asm("mov.b64 {%0, %1}, %2;" : "=f"(f.x), "=f"(f.y) : "l"(v)); return f;
}

union F4U { float4 f4; u64 u[2]; };

// ---------------------------------------------------------------------------
// Kernel 1: build CSR row pointers from sorted edge_rows (shfl for neighbor)
// ---------------------------------------------------------------------------
__global__ void build_row_ptr_kernel(const int* __restrict__ rows, int E) {
    int e    = blockIdx.x * blockDim.x + threadIdx.x;
    int lane = threadIdx.x & 31;
    int ee   = min(e, E - 1);
    int r    = rows[ee];
    int rp   = 0;
    if (lane == 0 && ee > 0) rp = rows[ee - 1];
    int rs = __shfl_up_sync(0xffffffff, r, 1);
    if (lane > 0) rp = rs;
    if (e >= E) return;
    if (e == 0) rp = -1;
    for (int j = rp + 1; j <= r; j++) g_row_ptr[j] = e;
    if (e == E - 1) {
        for (int j = r + 1; j <= N_NODES; j++) g_row_ptr[j] = E;
    }
}

// ---------------------------------------------------------------------------
// Kernel 2: transpose W ([j][k] row-major) -> g_Wt ([k][j])
// ---------------------------------------------------------------------------
__global__ void transpose_w_kernel(const float* __restrict__ W) {
    int j = blockIdx.x;          // 128 blocks
    int k = threadIdx.x;         // 128 threads
    g_Wt[k * D + j] = W[j * D + k];
}

// ---------------------------------------------------------------------------
// Kernel 3: SpMM — one warp per node; metadata fetched cooperatively
// (1 coalesced load per 32 edges) and distributed via shuffle.
// ---------------------------------------------------------------------------
__global__ void __launch_bounds__(256) spmm_kernel(const int*   __restrict__ cols,
                                                   const float* __restrict__ vals,
                                                   const float* __restrict__ h) {
    int gwarp = (blockIdx.x * blockDim.x + threadIdx.x) >> 5;
    int lane  = threadIdx.x & 31;
    if (gwarp >= N_NODES) return;

    int s = g_row_ptr[gwarp];
    int e = g_row_ptr[gwarp + 1];

    float4 acc = make_float4(0.f, 0.f, 0.f, 0.f);

    for (int base = s; base < e; base += 32) {
        int   idx = base + lane;
        int   c   = 0;
        float v   = 0.f;
        if (idx < e) {
            c = __ldg(&cols[idx]);     // coalesced
            v = __ldg(&vals[idx]);     // coalesced
        }
        int cnt = min(32, e - base);
        #pragma unroll 4
        for (int j = 0; j < cnt; j++) {
            int   cc = __shfl_sync(0xffffffff, c, j);
            float vv = __shfl_sync(0xffffffff, v, j);
            float4 hv = __ldg((const float4*)(h + (size_t)cc * D) + lane); // 512B coalesced
            acc.x += vv * hv.x;
            acc.y += vv * hv.y;
            acc.z += vv * hv.z;
            acc.w += vv * hv.w;
        }
    }
    ((float4*)(g_agg + (size_t)gwarp * D))[lane] = acc;
}

// ---------------------------------------------------------------------------
// Kernel 4: out = relu(agg @ W^T + b) with packed f32x2 FMA.
// 512 threads; block tile 128 nodes x 128 cols; thread tile 4 nodes x 8 cols
// (cols {tx*4..tx*4+3} and {64+tx*4..+3} as 4 f32x2 accumulator pairs).
// ---------------------------------------------------------------------------
__global__ void __launch_bounds__(512, 1) gemm_bias_relu_kernel(const float* __restrict__ b,
                                                                float* __restrict__ out) {
    extern __shared__ float sm[];
    float* As = sm;             // [MT][D]  node-major (reads ty-broadcast)
    float* Ws = sm + MT * D;    // [D][D]   k-major

    const int tid   = threadIdx.x;     // 0..511
    const int node0 = blockIdx.x * MT;
    const int tx    = tid & 15;        // 16 col groups
    const int ty    = tid >> 4;        // 32 node groups (4 nodes each)

    // Load Wt (k-major, contiguous) into shared — coalesced, conflict-free.
    for (int i = tid; i < (D * D) / 4; i += 512)
        ((float4*)Ws)[i] = ((const float4*)g_Wt)[i];

    // Load agg tile [MT][D], zero-pad out-of-range nodes.
    for (int i = tid; i < (MT * D) / 4; i += 512) {
        int n  = (i * 4) / D;
        int gn = node0 + n;
        float4 a4 = (gn < N_NODES)
                  ? ((const float4*)(g_agg + (size_t)gn * D))[(i * 4 % D) >> 2]
                  : make_float4(0.f, 0.f, 0.f, 0.f);
        ((float4*)As)[i] = a4;
    }
    __syncthreads();

    u64 acc[4][4];
    #pragma unroll
    for (int nn = 0; nn < 4; nn++)
        #pragma unroll
        for (int jp = 0; jp < 4; jp++)
            acc[nn][jp] = pack2(0.f, 0.f);

    for (int kk = 0; kk < D; kk += 4) {
        float4 a4[4];
        #pragma unroll
        for (int nn = 0; nn < 4; nn++)
            a4[nn] = *(const float4*)(As + (ty * 4 + nn) * D + kk);   // broadcast (2 addrs/warp)

        #pragma unroll
        for (int t = 0; t < 4; t++) {
            const float* wr = Ws + (kk + t) * D;
            F4U wA, wB;
            wA.f4 = *(const float4*)(wr + tx * 4);        // cols tx*4..+3
            wB.f4 = *(const float4*)(wr + 64 + tx * 4);   // cols 64+tx*4..+3
            #pragma unroll
            for (int nn = 0; nn < 4; nn++) {
                const float* ap = &a4[nn].x;
                u64 a2 = pack2(ap[t], ap[t]);
                acc[nn][0] = fma2(a2, wA.u[0], acc[nn][0]);
                acc[nn][1] = fma2(a2, wA.u[1], acc[nn][1]);
                acc[nn][2] = fma2(a2, wB.u[0], acc[nn][2]);
                acc[nn][3] = fma2(a2, wB.u[1], acc[nn][3]);
            }
        }
    }

    // Epilogue: + b, relu, two float4 stores per node.
    float4 bA = *(const float4*)(b + tx * 4);
    float4 bB = *(const float4*)(b + 64 + tx * 4);

    #pragma unroll
    for (int nn = 0; nn < 4; nn++) {
        int gn = node0 + ty * 4 + nn;
        if (gn < N_NODES) {
            float2 p0 = unpack2(acc[nn][0]);
            float2 p1 = unpack2(acc[nn][1]);
            float2 p2 = unpack2(acc[nn][2]);
            float2 p3 = unpack2(acc[nn][3]);
            float4 oA, oB;
            oA.x = fmaxf(p0.x + bA.x, 0.f);
            oA.y = fmaxf(p0.y + bA.y, 0.f);
            oA.z = fmaxf(p1.x + bA.z, 0.f);
            oA.w = fmaxf(p1.y + bA.w, 0.f);
            oB.x = fmaxf(p2.x + bB.x, 0.f);
            oB.y = fmaxf(p2.y + bB.y, 0.f);
            oB.z = fmaxf(p3.x + bB.z, 0.f);
            oB.w = fmaxf(p3.y + bB.w, 0.f);
            *(float4*)(out + (size_t)gn * D + tx * 4)      = oA;
            *(float4*)(out + (size_t)gn * D + 64 + tx * 4) = oB;
        }
    }
}

// ---------------------------------------------------------------------------
// Launch
// ---------------------------------------------------------------------------
extern "C" void kernel_launch(void* const* d_in, const int* in_sizes, int n_in,
                              void* d_out, int out_size) {
    const int*   edge_rows = (const int*)  d_in[0];
    const int*   edge_cols = (const int*)  d_in[1];
    const float* edge_vals = (const float*)d_in[2];
    const float* h         = (const float*)d_in[3];
    const float* W         = (const float*)d_in[4];
    const float* b         = (const float*)d_in[5];
    float*       out       = (float*)d_out;
    const int E = in_sizes[0];

    // 1) CSR row pointers
    build_row_ptr_kernel<<<(E + 255) / 256, 256>>>(edge_rows, E);

    // 2) W transpose (k-major) for conflict-free GEMM loads
    transpose_w_kernel<<<D, D>>>(W);

    // 3) SpMM: one warp per node
    {
        long long total_threads = (long long)N_NODES * 32;
        int blocks = (int)((total_threads + 255) / 256);
        spmm_kernel<<<blocks, 256>>>(edge_cols, edge_vals, h);
    }

    // 4) GEMM + bias + relu (f32x2 packed)
    cudaFuncSetAttribute(gemm_bias_relu_kernel,
                         cudaFuncAttributeMaxDynamicSharedMemorySize,
                         GEMM_SMEM_BYTES);
    gemm_bias_relu_kernel<<<(N_NODES + MT - 1) / MT, 512, GEMM_SMEM_BYTES>>>(b, out);
}

// round 4
// speedup vs baseline: 1.9789x; 1.1316x over previous
#include <cuda_runtime.h>
#include <cuda_fp16.h>

#define N_NODES 100000
#define D 128
#define MT 256                                     // nodes per GEMM block
#define GEMM_SMEM_BYTES ((MT * D + D * D) * 4)     // As(128KB) + Ws(64KB) = 192KB

typedef unsigned long long u64;

// Scratch (allocation-free rule: __device__ globals)
__device__ int            g_row_ptr[N_NODES + 1];
__device__ float          g_agg[(size_t)N_NODES * D];
__device__ float          g_Wt[D * D];             // W transposed: [k][j]
__device__ unsigned short g_h16[(size_t)N_NODES * D];  // h in fp16

// ---- packed f32x2 helpers (sm_100+) ---------------------------------------
__device__ __forceinline__ u64 pack2(float x, float y) {
    u64 r; asm("mov.b64 %0, {%1, %2};" : "=l"(r) : "f"(x), "f"(y)); return r;
}
__device__ __forceinline__ u64 fma2(u64 a, u64 b, u64 c) {
    u64 d; asm("fma.rn.f32x2 %0, %1, %2, %3;" : "=l"(d) : "l"(a), "l"(b), "l"(c));
    return d;
}
__device__ __forceinline__ float2 unpack2(u64 v) {
    float2 f; asm("mov.b64 {%0, %1}, %2;" : "=f"(f.x), "=f"(f.y) : "l"(v)); return f;
}

union F4U { float4 f4; u64 u[2]; };

// ---------------------------------------------------------------------------
// Kernel 1: build CSR row pointers from sorted edge_rows (shfl for neighbor)
// ---------------------------------------------------------------------------
__global__ void build_row_ptr_kernel(const int* __restrict__ rows, int E) {
    int e    = blockIdx.x * blockDim.x + threadIdx.x;
    int lane = threadIdx.x & 31;
    int ee   = min(e, E - 1);
    int r    = rows[ee];
    int rp   = 0;
    if (lane == 0 && ee > 0) rp = rows[ee - 1];
    int rs = __shfl_up_sync(0xffffffff, r, 1);
    if (lane > 0) rp = rs;
    if (e >= E) return;
    if (e == 0) rp = -1;
    for (int j = rp + 1; j <= r; j++) g_row_ptr[j] = e;
    if (e == E - 1) {
        for (int j = r + 1; j <= N_NODES; j++) g_row_ptr[j] = E;
    }
}

// ---------------------------------------------------------------------------
// Kernel 2: transpose W -> g_Wt ([k][j])
// ---------------------------------------------------------------------------
__global__ void transpose_w_kernel(const float* __restrict__ W) {
    int j = blockIdx.x;
    int k = threadIdx.x;
    g_Wt[k * D + j] = W[j * D + k];
}

// ---------------------------------------------------------------------------
// Kernel 3: convert h (fp32) -> g_h16 (fp16), vectorized
// ---------------------------------------------------------------------------
__global__ void __launch_bounds__(256) convert_h_kernel(const float* __restrict__ h) {
    int i = blockIdx.x * blockDim.x + threadIdx.x;          // one float4 per thread
    const int total = (N_NODES * D) / 4;
    if (i >= total) return;
    float4 f = __ldg(((const float4*)h) + i);
    __half2 a = __floats2half2_rn(f.x, f.y);
    __half2 b = __floats2half2_rn(f.z, f.w);
    uint2 packed;
    packed.x = *(unsigned int*)&a;
    packed.y = *(unsigned int*)&b;
    ((uint2*)g_h16)[i] = packed;
}

// ---------------------------------------------------------------------------
// Kernel 4: SpMM on fp16 h — one warp per node, fp32 accumulate.
// 256B per gathered row (half the L2 traffic of fp32).
// ---------------------------------------------------------------------------
__global__ void __launch_bounds__(256) spmm_kernel(const int*   __restrict__ cols,
                                                   const float* __restrict__ vals) {
    int gwarp = (blockIdx.x * blockDim.x + threadIdx.x) >> 5;
    int lane  = threadIdx.x & 31;
    if (gwarp >= N_NODES) return;

    int s = g_row_ptr[gwarp];
    int e = g_row_ptr[gwarp + 1];

    float4 acc = make_float4(0.f, 0.f, 0.f, 0.f);

    for (int base = s; base < e; base += 32) {
        int   idx = base + lane;
        int   c   = 0;
        float v   = 0.f;
        if (idx < e) {
            c = __ldg(&cols[idx]);     // coalesced
            v = __ldg(&vals[idx]);     // coalesced
        }
        int cnt = min(32, e - base);
        #pragma unroll 4
        for (int j = 0; j < cnt; j++) {
            int   cc = __shfl_sync(0xffffffff, c, j);
            float vv = __shfl_sync(0xffffffff, v, j);
            uint2 hv = __ldg((const uint2*)(g_h16 + (size_t)cc * D) + lane); // 256B coalesced
            float2 f0 = __half22float2(*(__half2*)&hv.x);
            float2 f1 = __half22float2(*(__half2*)&hv.y);
            acc.x += vv * f0.x;
            acc.y += vv * f0.y;
            acc.z += vv * f1.x;
            acc.w += vv * f1.y;
        }
    }
    ((float4*)(g_agg + (size_t)gwarp * D))[lane] = acc;
}

// ---------------------------------------------------------------------------
// Kernel 5: out = relu(agg @ W^T + b), f32x2 packed, 8x8 thread tile.
// 512 threads; block tile 256 nodes x 128 cols; thread: 8 nodes x 8 cols.
// ---------------------------------------------------------------------------
__global__ void __launch_bounds__(512, 1) gemm_bias_relu_kernel(const float* __restrict__ b,
                                                                float* __restrict__ out) {
    extern __shared__ float sm[];
    float* As = sm;             // [MT][D]  node-major
    float* Ws = sm + MT * D;    // [D][D]   k-major

    const int tid   = threadIdx.x;     // 0..511
    const int node0 = blockIdx.x * MT;
    const int tx    = tid & 15;        // 16 col groups (8 cols each)
    const int ty    = tid >> 4;        // 32 node groups (8 nodes each)

    // Load Wt (k-major) into shared — coalesced, conflict-free.
    for (int i = tid; i < (D * D) / 4; i += 512)
        ((float4*)Ws)[i] = ((const float4*)g_Wt)[i];

    // Load agg tile [MT][D], zero-pad out-of-range nodes.
    for (int i = tid; i < (MT * D) / 4; i += 512) {
        int n  = (i * 4) / D;
        int gn = node0 + n;
        float4 a4 = (gn < N_NODES)
                  ? ((const float4*)(g_agg + (size_t)gn * D))[(i * 4 % D) >> 2]
                  : make_float4(0.f, 0.f, 0.f, 0.f);
        ((float4*)As)[i] = a4;
    }
    __syncthreads();

    u64 acc[8][4];
    #pragma unroll
    for (int nn = 0; nn < 8; nn++)
        #pragma unroll
        for (int jp = 0; jp < 4; jp++)
            acc[nn][jp] = pack2(0.f, 0.f);

    for (int kk = 0; kk < D; kk += 4) {
        float4 a4[8];
        #pragma unroll
        for (int nn = 0; nn < 8; nn++)
            a4[nn] = *(const float4*)(As + (ty * 8 + nn) * D + kk);   // 2 distinct/warp

        #pragma unroll
        for (int t = 0; t < 4; t++) {
            const float* wr = Ws + (kk + t) * D;
            F4U wA, wB;
            wA.f4 = *(const float4*)(wr + tx * 4);
            wB.f4 = *(const float4*)(wr + 64 + tx * 4);
            #pragma unroll
            for (int nn = 0; nn < 8; nn++) {
                const float* ap = &a4[nn].x;
                u64 a2 = pack2(ap[t], ap[t]);
                acc[nn][0] = fma2(a2, wA.u[0], acc[nn][0]);
                acc[nn][1] = fma2(a2, wA.u[1], acc[nn][1]);
                acc[nn][2] = fma2(a2, wB.u[0], acc[nn][2]);
                acc[nn][3] = fma2(a2, wB.u[1], acc[nn][3]);
            }
        }
    }

    // Epilogue: + b, relu, two float4 stores per node.
    float4 bA = *(const float4*)(b + tx * 4);
    float4 bB = *(const float4*)(b + 64 + tx * 4);

    #pragma unroll
    for (int nn = 0; nn < 8; nn++) {
        int gn = node0 + ty * 8 + nn;
        if (gn < N_NODES) {
            float2 p0 = unpack2(acc[nn][0]);
            float2 p1 = unpack2(acc[nn][1]);
            float2 p2 = unpack2(acc[nn][2]);
            float2 p3 = unpack2(acc[nn][3]);
            float4 oA, oB;
            oA.x = fmaxf(p0.x + bA.x, 0.f);
            oA.y = fmaxf(p0.y + bA.y, 0.f);
            oA.z = fmaxf(p1.x + bA.z, 0.f);
            oA.w = fmaxf(p1.y + bA.w, 0.f);
            oB.x = fmaxf(p2.x + bB.x, 0.f);
            oB.y = fmaxf(p2.y + bB.y, 0.f);
            oB.z = fmaxf(p3.x + bB.z, 0.f);
            oB.w = fmaxf(p3.y + bB.w, 0.f);
            *(float4*)(out + (size_t)gn * D + tx * 4)      = oA;
            *(float4*)(out + (size_t)gn * D + 64 + tx * 4) = oB;
        }
    }
}

// ---------------------------------------------------------------------------
// Launch
// ---------------------------------------------------------------------------
extern "C" void kernel_launch(void* const* d_in, const int* in_sizes, int n_in,
                              void* d_out, int out_size) {
    const int*   edge_rows = (const int*)  d_in[0];
    const int*   edge_cols = (const int*)  d_in[1];
    const float* edge_vals = (const float*)d_in[2];
    const float* h         = (const float*)d_in[3];
    const float* W         = (const float*)d_in[4];
    const float* b         = (const float*)d_in[5];
    float*       out       = (float*)d_out;
    const int E = in_sizes[0];

    // 1) CSR row pointers
    build_row_ptr_kernel<<<(E + 255) / 256, 256>>>(edge_rows, E);

    // 2) W transpose (k-major)
    transpose_w_kernel<<<D, D>>>(W);

    // 3) h -> fp16
    {
        int total = (N_NODES * D) / 4;
        convert_h_kernel<<<(total + 255) / 256, 256>>>(h);
    }

    // 4) SpMM (fp16 gather, fp32 accumulate)
    {
        long long total_threads = (long long)N_NODES * 32;
        int blocks = (int)((total_threads + 255) / 256);
        spmm_kernel<<<blocks, 256>>>(edge_cols, edge_vals);
    }

    // 5) GEMM + bias + relu (f32x2 packed, 8x8 tile)
    cudaFuncSetAttribute(gemm_bias_relu_kernel,
                         cudaFuncAttributeMaxDynamicSharedMemorySize,
                         GEMM_SMEM_BYTES);
    gemm_bias_relu_kernel<<<(N_NODES + MT - 1) / MT, 512, GEMM_SMEM_BYTES>>>(b, out);
}